// round 10
// baseline (speedup 1.0000x reference)
#include <cuda_runtime.h>
#include <cuda_fp16.h>
#include <cstdint>

// Problem constants (fixed by setup_inputs)
#define B_   8
#define QL   1024
#define SL   2048
#define DM   1024
#define H_   16
#define DH   64
#define QT   128          // q rows per CTA
#define STT  128          // s cols per chunk (K1)
#define NCH  (SL/STT)     // 16

#define KS_S 68           // K tile stride: banks 4g+lt distinct for B-frags
// K1 smem floats: 2 x (128*68) K dbuf + mask 2048 + Rs 512
#define K1_SMEM_FLOATS (2*STT*KS_S + SL + 512)

// K2 (normalize + PV GEMM) config
#define KC   64           // k-chunk (s dimension)
#define NKC  (SL/KC)      // 32
#define AS_H 72           // e tile stride in HALVES (36 words -> banks 4g+lt)
#define VS_S 68           // V tile stride in floats (banks 8lt+g with k-pair rows)
#define K2_SMEM_BYTES (2*QT*AS_H*2 + 2*KC*VS_S*4 + 512)

// scratch: per-(b,h,q) 1/rowsum, and fp16 e matrix
__device__ float  InvG[(size_t)B_ * H_ * QL];
__device__ __half EG[(size_t)B_ * H_ * QL * SL];   // 512 MB

__device__ __forceinline__ uint32_t tf32b(float x) {
    uint32_t u;
    asm("cvt.rna.tf32.f32 %0, %1;" : "=r"(u) : "f"(x));
    return u;
}

__device__ __forceinline__ void mma8(float d[4], const uint32_t a[4], const uint32_t b[2]) {
    asm("mma.sync.aligned.m16n8k8.row.col.f32.tf32.tf32.f32 "
        "{%0,%1,%2,%3},{%4,%5,%6,%7},{%8,%9},{%0,%1,%2,%3};\n"
        : "+f"(d[0]), "+f"(d[1]), "+f"(d[2]), "+f"(d[3])
        : "r"(a[0]), "r"(a[1]), "r"(a[2]), "r"(a[3]), "r"(b[0]), "r"(b[1]));
}

__device__ __forceinline__ void cp_async16(uint32_t smem_addr, const void* gptr) {
    asm volatile("cp.async.cg.shared.global [%0], [%1], 16;\n"
                 :: "r"(smem_addr), "l"(gptr));
}
__device__ __forceinline__ void cp_commit() {
    asm volatile("cp.async.commit_group;\n");
}
__device__ __forceinline__ void cp_wait1() {
    asm volatile("cp.async.wait_group 1;\n");
}

// ===================== K1: single QK pass -> e=exp(z)*mask (fp16) + inv =====================
// 512 threads, warp grid 4(q) x 4(s), warp tile 32q x 32s. Q-frags in registers.
extern "C" __global__ void __launch_bounds__(512, 1)
mha_qk_kernel(const float* __restrict__ Qg, const float* __restrict__ Kg,
              const int* __restrict__ Mg) {
    extern __shared__ float smf[];
    float* Ks = smf;                 // 2 x 128 x KS_S (raw f32, cvt at frag load)
    float* Ms = Ks + 2 * STT * KS_S; // mask row, SL floats
    float* Rs = Ms + SL;             // 4 x 128 partial rowsums (per wn)

    const int tid = threadIdx.x;
    const int lane = tid & 31, wid = tid >> 5;
    const int g = lane >> 2, lt = lane & 3;
    const int wm = wid >> 2, wn = wid & 3;
    const int b = blockIdx.z, h = blockIdx.y, q0 = blockIdx.x * QT;

    const float* gkb = Kg + ((size_t)b * SL) * DM + h * DH;
    const uint32_t ks_base = (uint32_t)__cvta_generic_to_shared(Ks);

    // mask row
    for (int j = tid; j < SL; j += 512) Ms[j] = (float)Mg[b * SL + j];

    // Q fragments -> registers (scale 1/8, tf32 RNA); rows wm*32 .. wm*32+31
    uint32_t qfr[2][8][4];
    {
        const float* gq = Qg + ((size_t)(b * QL + q0)) * DM + h * DH;
        #pragma unroll
        for (int mi = 0; mi < 2; mi++) {
            int r = wm * 32 + mi * 16 + g;
            #pragma unroll
            for (int kk = 0; kk < 8; kk++) {
                qfr[mi][kk][0] = tf32b(__ldg(gq + (size_t)r * DM + kk * 8 + lt) * 0.125f);
                qfr[mi][kk][1] = tf32b(__ldg(gq + (size_t)(r + 8) * DM + kk * 8 + lt) * 0.125f);
                qfr[mi][kk][2] = tf32b(__ldg(gq + (size_t)r * DM + kk * 8 + lt + 4) * 0.125f);
                qfr[mi][kk][3] = tf32b(__ldg(gq + (size_t)(r + 8) * DM + kk * 8 + lt + 4) * 0.125f);
            }
        }
    }

    // staging coords: 512 threads x 4 float4 = 128 rows x 64 cols
    int srow[4], scol[4];
    #pragma unroll
    for (int j = 0; j < 4; j++) {
        int idx = tid + j * 512;
        srow[j] = idx >> 4;
        scol[j] = (idx & 15) << 2;
    }
    auto stage = [&](int sc, int bi) {
        const float* gk = gkb + (size_t)sc * STT * DM;
        const uint32_t kd = ks_base + (uint32_t)(bi * STT * KS_S) * 4;
        #pragma unroll
        for (int j = 0; j < 4; j++)
            cp_async16(kd + (uint32_t)(srow[j] * KS_S + scol[j]) * 4,
                       gk + (size_t)srow[j] * DM + scol[j]);
        cp_commit();
    };

    float rs_acc[2][2] = {{0.f, 0.f}, {0.f, 0.f}};
    stage(0, 0);

    for (int sc = 0; sc < NCH; sc++) {
        if (sc + 1 < NCH) stage(sc + 1, (sc + 1) & 1);
        else cp_commit();
        cp_wait1();
        __syncthreads();
        const float* Kc = Ks + (sc & 1) * STT * KS_S;

        float acc[2][4][4];
        #pragma unroll
        for (int mi = 0; mi < 2; mi++)
            #pragma unroll
            for (int ni = 0; ni < 4; ni++)
                #pragma unroll
                for (int j = 0; j < 4; j++) acc[mi][ni][j] = 0.f;

        #pragma unroll
        for (int kk = 0; kk < 8; kk++) {
            #pragma unroll
            for (int ni = 0; ni < 4; ni++) {
                int c = wn * 32 + ni * 8 + g;
                uint32_t bfr[2];
                bfr[0] = tf32b(Kc[c * KS_S + kk * 8 + lt]);
                bfr[1] = tf32b(Kc[c * KS_S + kk * 8 + lt + 4]);
                mma8(acc[0][ni], qfr[0][kk], bfr);
                mma8(acc[1][ni], qfr[1][kk], bfr);
            }
        }

        // epilogue: e = exp(z)*mask -> EG (fp16 RN), rowsum from ROUNDED values
        const int s0 = sc * STT;
        #pragma unroll
        for (int mi = 0; mi < 2; mi++)
            #pragma unroll
            for (int half = 0; half < 2; half++) {
                int r = wm * 32 + mi * 16 + g + half * 8;
                __half* ge = EG + ((size_t)((b * H_ + h) * QL + q0 + r)) * SL
                                + s0 + wn * 32;
                float rloc = 0.f;
                #pragma unroll
                for (int ni = 0; ni < 4; ni++) {
                    int mc = s0 + wn * 32 + ni * 8 + 2 * lt;
                    float ex = __expf(acc[mi][ni][half * 2 + 0]) * Ms[mc];
                    float ey = __expf(acc[mi][ni][half * 2 + 1]) * Ms[mc + 1];
                    __half2 hv = __floats2half2_rn(ex, ey);
                    float2 fr = __half22float2(hv);
                    rloc += fr.x + fr.y;
                    __stcs((uint32_t*)(ge + ni * 8 + 2 * lt), *(uint32_t*)&hv);
                }
                rs_acc[mi][half] += rloc;
            }
        __syncthreads();   // buffer (sc&1) free before it is restaged at sc+2
    }

    // reduce rowsums: over lt within quad, then over wn via smem
    #pragma unroll
    for (int mi = 0; mi < 2; mi++)
        #pragma unroll
        for (int half = 0; half < 2; half++) {
            float v = rs_acc[mi][half];
            v += __shfl_xor_sync(0xffffffffu, v, 1);
            v += __shfl_xor_sync(0xffffffffu, v, 2);
            if (lt == 0) {
                int r = wm * 32 + mi * 16 + g + half * 8;
                Rs[wn * 128 + r] = v;
            }
        }
    __syncthreads();
    if (tid < QT) {
        float s = Rs[tid] + Rs[128 + tid] + Rs[256 + tid] + Rs[384 + tid];
        InvG[((size_t)(b * H_ + h)) * QL + q0 + tid] = 1.0f / (s + 1e-13f);
    }
}

// ===================== K2: attn = e*inv (write f32) + O = (e @ V) * inv =====================
extern "C" __global__ void __launch_bounds__(256, 2)
mha_pv_kernel(const float* __restrict__ Vg, float* __restrict__ Ag,
              float* __restrict__ Og) {
    extern __shared__ float smf[];
    __half* As = (__half*)smf;                       // 2 x 128 x AS_H halves
    float* Vs = (float*)(As + 2 * QT * AS_H);        // 2 x 64 x VS_S floats
    float* Iv = Vs + 2 * KC * VS_S;                  // 128 inv values

    const int tid = threadIdx.x;
    const int lane = tid & 31, wid = tid >> 5;
    const int g = lane >> 2, lt = lane & 3;
    const int wm = wid >> 1, wn = wid & 1;   // 4(q) x 2(dv), warp tile 32x32
    const int b = blockIdx.z, h = blockIdx.y, q0 = blockIdx.x * QT;

    const uint32_t as_base = (uint32_t)__cvta_generic_to_shared(As);
    const uint32_t vs_base = (uint32_t)__cvta_generic_to_shared(Vs);

    if (tid < QT) Iv[tid] = InvG[((size_t)(b * H_ + h)) * QL + q0 + tid];

    // A staging: 128 rows x 64 halves = 128B/row -> 8 x 16B ops/row, 1024 total
    int ar[4], ac[4];
    #pragma unroll
    for (int j = 0; j < 4; j++) {
        int idx = tid + j * 256;
        ar[j] = idx >> 3;
        ac[j] = (idx & 7) * 8;     // half units
    }
    // V staging: 64 rows x 64 floats
    int vr[4], vc[4];
    #pragma unroll
    for (int j = 0; j < 4; j++) {
        int idx = tid + j * 256;
        vr[j] = idx >> 4;
        vc[j] = (idx & 15) << 2;
    }

    const __half* geb = EG + ((size_t)((b * H_ + h) * QL + q0)) * SL;  // row stride SL
    float* gab = Ag + ((size_t)((b * QL + q0) * H_ + h)) * SL;         // row stride H_*SL
    const float* gvb = Vg + ((size_t)b * SL) * DM + h * DH;

    auto stage = [&](int kc, int bi) {
        const int s0 = kc * KC;
        const uint32_t ad = as_base + (uint32_t)(bi * QT * AS_H) * 2;
        #pragma unroll
        for (int j = 0; j < 4; j++)
            cp_async16(ad + (uint32_t)(ar[j] * AS_H + ac[j]) * 2,
                       geb + (size_t)ar[j] * SL + s0 + ac[j]);
        const uint32_t vd = vs_base + (uint32_t)(bi * KC * VS_S) * 4;
        #pragma unroll
        for (int j = 0; j < 4; j++)
            cp_async16(vd + (uint32_t)(vr[j] * VS_S + vc[j]) * 4,
                       gvb + (size_t)(kc * KC + vr[j]) * DM + vc[j]);
        cp_commit();
    };

    float oacc[2][4][4];
    #pragma unroll
    for (int mi = 0; mi < 2; mi++)
        #pragma unroll
        for (int ni = 0; ni < 4; ni++)
            #pragma unroll
            for (int j = 0; j < 4; j++) oacc[mi][ni][j] = 0.f;

    stage(0, 0);

    for (int kc = 0; kc < NKC; kc++) {
        if (kc + 1 < NKC) stage(kc + 1, (kc + 1) & 1);
        else cp_commit();
        cp_wait1();
        __syncthreads();

        const __half* Ac = As + (kc & 1) * QT * AS_H;
        const float* Vc = Vs + (kc & 1) * KC * VS_S;

        // PV mma; k slot lt |-> k=2lt, slot lt+4 |-> k=2lt+1 (A and B consistent)
        #pragma unroll
        for (int kk = 0; kk < 8; kk++) {
            uint32_t afr[2][4];
            #pragma unroll
            for (int mi = 0; mi < 2; mi++) {
                int r = wm * 32 + mi * 16 + g;
                __half2 h0 = *(const __half2*)(Ac + r * AS_H + kk * 8 + 2 * lt);
                __half2 h1 = *(const __half2*)(Ac + (r + 8) * AS_H + kk * 8 + 2 * lt);
                float2 f0 = __half22float2(h0);
                float2 f1 = __half22float2(h1);
                afr[mi][0] = __float_as_uint(f0.x);   // fp16 -> tf32 exact
                afr[mi][1] = __float_as_uint(f1.x);
                afr[mi][2] = __float_as_uint(f0.y);
                afr[mi][3] = __float_as_uint(f1.y);
            }
            #pragma unroll
            for (int ni = 0; ni < 4; ni++) {
                int c = wn * 32 + ni * 8 + g;
                uint32_t bfr[2];
                bfr[0] = tf32b(Vc[(kk * 8 + 2 * lt) * VS_S + c]);
                bfr[1] = tf32b(Vc[(kk * 8 + 2 * lt + 1) * VS_S + c]);
                mma8(oacc[0][ni], afr[0], bfr);
                mma8(oacc[1][ni], afr[1], bfr);
            }
        }

        // normalized attention write: attn = float(e_fp16) * inv[row]
        const int s0 = kc * KC;
        #pragma unroll
        for (int j = 0; j < 8; j++) {
            int idx = tid + j * 256;            // 128 x 64 floats / 4
            int r = idx >> 4, c4 = (idx & 15) << 2;
            __half2 ha = *(const __half2*)(Ac + r * AS_H + c4);
            __half2 hb = *(const __half2*)(Ac + r * AS_H + c4 + 2);
            float2 fa = __half22float2(ha), fb = __half22float2(hb);
            float iv = Iv[r];
            float4 v = make_float4(fa.x * iv, fa.y * iv, fb.x * iv, fb.y * iv);
            __stcs((float4*)(gab + (size_t)r * (H_ * SL) + s0 + c4), v);
        }
        __syncthreads();   // buffer free before restage
    }

    // ---- write O tile, scaled by inv per row ----
    #pragma unroll
    for (int mi = 0; mi < 2; mi++) {
        int r = wm * 32 + mi * 16 + g;
        float iv0 = Iv[r], iv1 = Iv[r + 8];
        float* go = Og + ((size_t)(b * QL + q0 + r)) * DM + h * DH + wn * 32;
        #pragma unroll
        for (int ni = 0; ni < 4; ni++) {
            int c = ni * 8 + 2 * lt;
            float2 v0; v0.x = oacc[mi][ni][0] * iv0; v0.y = oacc[mi][ni][1] * iv0;
            float2 v1; v1.x = oacc[mi][ni][2] * iv1; v1.y = oacc[mi][ni][3] * iv1;
            __stcs((float2*)(go + c), v0);
            __stcs((float2*)(go + (size_t)8 * DM + c), v1);
        }
    }
}

extern "C" void kernel_launch(void* const* d_in, const int* in_sizes, int n_in,
                              void* d_out, int out_size) {
    const float* Qg = (const float*)d_in[0];
    const float* Kg = (const float*)d_in[1];
    const float* Vg = (const float*)d_in[2];
    const int*   Mg = (const int*)d_in[3];

    float* Og = (float*)d_out;
    float* Ag = Og + (size_t)B_ * QL * DM;   // attention region of d_out

    cudaFuncSetAttribute(mha_qk_kernel,
                         cudaFuncAttributeMaxDynamicSharedMemorySize,
                         K1_SMEM_FLOATS * (int)sizeof(float));
    cudaFuncSetAttribute(mha_pv_kernel,
                         cudaFuncAttributeMaxDynamicSharedMemorySize,
                         K2_SMEM_BYTES);

    dim3 grid(QL / QT, H_, B_);
    mha_qk_kernel<<<grid, 512, K1_SMEM_FLOATS * sizeof(float)>>>(Qg, Kg, Mg);
    mha_pv_kernel<<<grid, 256, K2_SMEM_BYTES>>>(Vg, Ag, Og);
}

// round 11
// speedup vs baseline: 1.4118x; 1.4118x over previous
#include <cuda_runtime.h>
#include <cstdint>

// Problem constants (fixed by setup_inputs)
#define B_   8
#define QL   1024
#define SL   2048
#define DM   1024
#define H_   16
#define DH   64
#define QT   128          // q rows per CTA
#define STT  128          // s cols per chunk (K1)
#define NCH  (SL/STT)     // 16

#define KS_S 68           // K tile stride: banks 4g+lt distinct for B-frags
// K1 smem floats: 3 x (128*68) K triple-buffer + mask 2048 + Rs 512
#define K1_SMEM_FLOATS (3*STT*KS_S + SL + 512)

// K2 (normalize + PV GEMM) config
#define KC   64           // k-chunk (s dimension)
#define NKC  (SL/KC)      // 32
#define AS_S 68           // e tile stride (A-frag conflict-free)
#define VS_S 72           // V tile stride (B-frag conflict-free)
#define K2_SMEM_FLOATS (2*QT*AS_S + 2*KC*VS_S + 128)

// per-(b,h,q) 1/rowsum scratch
__device__ float InvG[(size_t)B_ * H_ * QL];

__device__ __forceinline__ uint32_t tf32b(float x) {
    uint32_t u;
    asm("cvt.rna.tf32.f32 %0, %1;" : "=r"(u) : "f"(x));
    return u;
}

__device__ __forceinline__ void mma8(float d[4], const uint32_t a[4], const uint32_t b[2]) {
    asm("mma.sync.aligned.m16n8k8.row.col.f32.tf32.tf32.f32 "
        "{%0,%1,%2,%3},{%4,%5,%6,%7},{%8,%9},{%0,%1,%2,%3};\n"
        : "+f"(d[0]), "+f"(d[1]), "+f"(d[2]), "+f"(d[3])
        : "r"(a[0]), "r"(a[1]), "r"(a[2]), "r"(a[3]), "r"(b[0]), "r"(b[1]));
}

__device__ __forceinline__ void cp_async16(uint32_t smem_addr, const void* gptr) {
    asm volatile("cp.async.cg.shared.global [%0], [%1], 16;\n"
                 :: "r"(smem_addr), "l"(gptr));
}
__device__ __forceinline__ void cp_commit() {
    asm volatile("cp.async.commit_group;\n");
}
__device__ __forceinline__ void cp_wait1() {
    asm volatile("cp.async.wait_group 1;\n");
}
__device__ __forceinline__ void cp_wait2() {
    asm volatile("cp.async.wait_group 2;\n");
}

// ===================== K1: single QK pass -> e=exp(z)*mask to gmem + inv =====================
// 512 threads, warp grid 4(q) x 4(s), warp tile 32q x 32s. Q-frags in registers.
// Triple-buffered cp.async K staging: wait at top of iter sc is for a group
// committed two iterations earlier -> latency fully hidden.
extern "C" __global__ void __launch_bounds__(512, 1)
mha_qk_kernel(const float* __restrict__ Qg, const float* __restrict__ Kg,
              const int* __restrict__ Mg, float* __restrict__ Ag) {
    extern __shared__ float smf[];
    float* Ks = smf;                 // 3 x 128 x KS_S (raw f32, cvt at frag load)
    float* Ms = Ks + 3 * STT * KS_S; // mask row, SL floats
    float* Rs = Ms + SL;             // 4 x 128 partial rowsums (per wn)

    const int tid = threadIdx.x;
    const int lane = tid & 31, wid = tid >> 5;
    const int g = lane >> 2, lt = lane & 3;
    const int wm = wid >> 2, wn = wid & 3;
    const int b = blockIdx.z, h = blockIdx.y, q0 = blockIdx.x * QT;

    const float* gkb = Kg + ((size_t)b * SL) * DM + h * DH;
    const uint32_t ks_base = (uint32_t)__cvta_generic_to_shared(Ks);

    // mask row
    for (int j = tid; j < SL; j += 512) Ms[j] = (float)Mg[b * SL + j];

    // Q fragments -> registers (scale 1/8, tf32 RNA); rows wm*32 .. wm*32+31
    uint32_t qfr[2][8][4];
    {
        const float* gq = Qg + ((size_t)(b * QL + q0)) * DM + h * DH;
        #pragma unroll
        for (int mi = 0; mi < 2; mi++) {
            int r = wm * 32 + mi * 16 + g;
            #pragma unroll
            for (int kk = 0; kk < 8; kk++) {
                qfr[mi][kk][0] = tf32b(__ldg(gq + (size_t)r * DM + kk * 8 + lt) * 0.125f);
                qfr[mi][kk][1] = tf32b(__ldg(gq + (size_t)(r + 8) * DM + kk * 8 + lt) * 0.125f);
                qfr[mi][kk][2] = tf32b(__ldg(gq + (size_t)r * DM + kk * 8 + lt + 4) * 0.125f);
                qfr[mi][kk][3] = tf32b(__ldg(gq + (size_t)(r + 8) * DM + kk * 8 + lt + 4) * 0.125f);
            }
        }
    }

    // staging coords: 512 threads x 4 float4 = 128 rows x 64 cols
    int srow[4], scol[4];
    #pragma unroll
    for (int j = 0; j < 4; j++) {
        int idx = tid + j * 512;
        srow[j] = idx >> 4;
        scol[j] = (idx & 15) << 2;
    }
    auto stage = [&](int sc, int bi) {
        const float* gk = gkb + (size_t)sc * STT * DM;
        const uint32_t kd = ks_base + (uint32_t)(bi * STT * KS_S) * 4;
        #pragma unroll
        for (int j = 0; j < 4; j++)
            cp_async16(kd + (uint32_t)(srow[j] * KS_S + scol[j]) * 4,
                       gk + (size_t)srow[j] * DM + scol[j]);
        cp_commit();
    };

    float rs_acc[2][2] = {{0.f, 0.f}, {0.f, 0.f}};
    stage(0, 0);
    stage(1, 1);

    for (int sc = 0; sc < NCH; sc++) {
        if (sc + 2 < NCH) stage(sc + 2, (sc + 2) % 3);
        else cp_commit();                 // keep group count consistent
        cp_wait2();                       // group for chunk sc complete
        __syncthreads();
        const float* Kc = Ks + (sc % 3) * STT * KS_S;

        float acc[2][4][4];
        #pragma unroll
        for (int mi = 0; mi < 2; mi++)
            #pragma unroll
            for (int ni = 0; ni < 4; ni++)
                #pragma unroll
                for (int j = 0; j < 4; j++) acc[mi][ni][j] = 0.f;

        #pragma unroll
        for (int kk = 0; kk < 8; kk++) {
            #pragma unroll
            for (int ni = 0; ni < 4; ni++) {
                int c = wn * 32 + ni * 8 + g;
                uint32_t bfr[2];
                bfr[0] = tf32b(Kc[c * KS_S + kk * 8 + lt]);
                bfr[1] = tf32b(Kc[c * KS_S + kk * 8 + lt + 4]);
                mma8(acc[0][ni], qfr[0][kk], bfr);
                mma8(acc[1][ni], qfr[1][kk], bfr);
            }
        }

        // epilogue: e = exp(z)*mask -> gmem (32B sector quads), rowsum partials in regs
        const int s0 = sc * STT;
        #pragma unroll
        for (int mi = 0; mi < 2; mi++)
            #pragma unroll
            for (int half = 0; half < 2; half++) {
                int r = wm * 32 + mi * 16 + g + half * 8;
                float* ga = Ag + ((size_t)((b * QL + q0 + r) * H_ + h)) * SL
                               + s0 + wn * 32;
                float rloc = 0.f;
                #pragma unroll
                for (int ni = 0; ni < 4; ni++) {
                    int mc = s0 + wn * 32 + ni * 8 + 2 * lt;
                    float2 ev;
                    ev.x = __expf(acc[mi][ni][half * 2 + 0]) * Ms[mc];
                    ev.y = __expf(acc[mi][ni][half * 2 + 1]) * Ms[mc + 1];
                    rloc += ev.x + ev.y;
                    __stcs((float2*)(ga + ni * 8 + 2 * lt), ev);
                }
                rs_acc[mi][half] += rloc;
            }
        __syncthreads();   // buffer sc%3 free before restage at iter sc+1
    }

    // reduce rowsums: over lt within quad, then over wn via smem
    #pragma unroll
    for (int mi = 0; mi < 2; mi++)
        #pragma unroll
        for (int half = 0; half < 2; half++) {
            float v = rs_acc[mi][half];
            v += __shfl_xor_sync(0xffffffffu, v, 1);
            v += __shfl_xor_sync(0xffffffffu, v, 2);
            if (lt == 0) {
                int r = wm * 32 + mi * 16 + g + half * 8;
                Rs[wn * 128 + r] = v;
            }
        }
    __syncthreads();
    if (tid < QT) {
        float s = Rs[tid] + Rs[128 + tid] + Rs[256 + tid] + Rs[384 + tid];
        InvG[((size_t)(b * H_ + h)) * QL + q0 + tid] = 1.0f / (s + 1e-13f);
    }
}

// ===================== K2: normalize attn + O = (e @ V) * inv =====================
extern "C" __global__ void __launch_bounds__(256, 2)
mha_pv_kernel(float* __restrict__ Ag, const float* __restrict__ Vg,
              float* __restrict__ Og) {
    extern __shared__ float smf[];
    float* As = smf;                   // 2 x 128 x AS_S (raw e)
    float* Vs = As + 2 * QT * AS_S;    // 2 x 64 x VS_S
    float* Iv = Vs + 2 * KC * VS_S;    // 128 inv values

    const int tid = threadIdx.x;
    const int lane = tid & 31, wid = tid >> 5;
    const int g = lane >> 2, lt = lane & 3;
    const int wm = wid >> 1, wn = wid & 1;   // 4(q) x 2(dv), warp tile 32x32
    const int b = blockIdx.z, h = blockIdx.y, q0 = blockIdx.x * QT;

    const uint32_t as_base = (uint32_t)__cvta_generic_to_shared(As);
    const uint32_t vs_base = (uint32_t)__cvta_generic_to_shared(Vs);

    if (tid < QT) Iv[tid] = InvG[((size_t)(b * H_ + h)) * QL + q0 + tid];

    int ar[8], ac[8];
    #pragma unroll
    for (int j = 0; j < 8; j++) {
        int idx = tid + j * 256;           // 128 x 64 floats / 4
        ar[j] = idx >> 4;
        ac[j] = (idx & 15) << 2;
    }
    int vr[4], vc[4];
    #pragma unroll
    for (int j = 0; j < 4; j++) {
        int idx = tid + j * 256;           // 64 x 64 floats / 4
        vr[j] = idx >> 4;
        vc[j] = (idx & 15) << 2;
    }

    float* gab = Ag + ((size_t)((b * QL + q0) * H_ + h)) * SL;  // row stride H_*SL
    const float* gvb = Vg + ((size_t)b * SL) * DM + h * DH;

    auto stage = [&](int kc, int bi) {
        const int s0 = kc * KC;
        const uint32_t ad = as_base + (uint32_t)(bi * QT * AS_S) * 4;
        #pragma unroll
        for (int j = 0; j < 8; j++)
            cp_async16(ad + (uint32_t)(ar[j] * AS_S + ac[j]) * 4,
                       gab + (size_t)ar[j] * (H_ * SL) + s0 + ac[j]);
        const uint32_t vd = vs_base + (uint32_t)(bi * KC * VS_S) * 4;
        #pragma unroll
        for (int j = 0; j < 4; j++)
            cp_async16(vd + (uint32_t)(vr[j] * VS_S + vc[j]) * 4,
                       gvb + (size_t)(kc * KC + vr[j]) * DM + vc[j]);
        cp_commit();
    };

    float oacc[2][4][4];
    #pragma unroll
    for (int mi = 0; mi < 2; mi++)
        #pragma unroll
        for (int ni = 0; ni < 4; ni++)
            #pragma unroll
            for (int j = 0; j < 4; j++) oacc[mi][ni][j] = 0.f;

    stage(0, 0);

    for (int kc = 0; kc < NKC; kc++) {
        if (kc + 1 < NKC) stage(kc + 1, (kc + 1) & 1);
        else cp_commit();
        cp_wait1();
        __syncthreads();

        const float* Ac = As + (kc & 1) * QT * AS_S;
        const float* Vc = Vs + (kc & 1) * KC * VS_S;

        // PV mma on raw e (RNA-rounded in registers)
        #pragma unroll
        for (int kk = 0; kk < 8; kk++) {
            uint32_t afr[2][4];
            #pragma unroll
            for (int mi = 0; mi < 2; mi++) {
                int r = wm * 32 + mi * 16 + g;
                afr[mi][0] = tf32b(Ac[r * AS_S + kk * 8 + lt]);
                afr[mi][1] = tf32b(Ac[(r + 8) * AS_S + kk * 8 + lt]);
                afr[mi][2] = tf32b(Ac[r * AS_S + kk * 8 + lt + 4]);
                afr[mi][3] = tf32b(Ac[(r + 8) * AS_S + kk * 8 + lt + 4]);
            }
            #pragma unroll
            for (int ni = 0; ni < 4; ni++) {
                int c = wn * 32 + ni * 8 + g;
                uint32_t bfr[2];
                bfr[0] = tf32b(Vc[(kk * 8 + lt) * VS_S + c]);
                bfr[1] = tf32b(Vc[(kk * 8 + lt + 4) * VS_S + c]);
                mma8(oacc[0][ni], afr[0], bfr);
                mma8(oacc[1][ni], afr[1], bfr);
            }
        }

        // normalized attention write-back: attn = e * inv[row]  (streaming, no reuse)
        const int s0 = kc * KC;
        #pragma unroll
        for (int j = 0; j < 8; j++) {
            float4 v = *(const float4*)(Ac + ar[j] * AS_S + ac[j]);
            float iv = Iv[ar[j]];
            v.x *= iv; v.y *= iv; v.z *= iv; v.w *= iv;
            __stwt((float4*)(gab + (size_t)ar[j] * (H_ * SL) + s0 + ac[j]), v);
        }
        __syncthreads();   // buffer free before restage
    }

    // ---- write O tile, scaled by inv per row ----
    #pragma unroll
    for (int mi = 0; mi < 2; mi++) {
        int r = wm * 32 + mi * 16 + g;
        float iv0 = Iv[r], iv1 = Iv[r + 8];
        float* go = Og + ((size_t)(b * QL + q0 + r)) * DM + h * DH + wn * 32;
        #pragma unroll
        for (int ni = 0; ni < 4; ni++) {
            int c = ni * 8 + 2 * lt;
            float2 v0; v0.x = oacc[mi][ni][0] * iv0; v0.y = oacc[mi][ni][1] * iv0;
            float2 v1; v1.x = oacc[mi][ni][2] * iv1; v1.y = oacc[mi][ni][3] * iv1;
            __stcs((float2*)(go + c), v0);
            __stcs((float2*)(go + (size_t)8 * DM + c), v1);
        }
    }
}

extern "C" void kernel_launch(void* const* d_in, const int* in_sizes, int n_in,
                              void* d_out, int out_size) {
    const float* Qg = (const float*)d_in[0];
    const float* Kg = (const float*)d_in[1];
    const float* Vg = (const float*)d_in[2];
    const int*   Mg = (const int*)d_in[3];

    float* Og = (float*)d_out;
    float* Ag = Og + (size_t)B_ * QL * DM;   // attention region of d_out

    cudaFuncSetAttribute(mha_qk_kernel,
                         cudaFuncAttributeMaxDynamicSharedMemorySize,
                         K1_SMEM_FLOATS * (int)sizeof(float));
    cudaFuncSetAttribute(mha_pv_kernel,
                         cudaFuncAttributeMaxDynamicSharedMemorySize,
                         K2_SMEM_FLOATS * (int)sizeof(float));

    dim3 grid(QL / QT, H_, B_);
    mha_qk_kernel<<<grid, 512, K1_SMEM_FLOATS * sizeof(float)>>>(Qg, Kg, Mg, Ag);
    mha_pv_kernel<<<grid, 256, K2_SMEM_FLOATS * sizeof(float)>>>(Ag, Vg, Og);
}

// round 12
// speedup vs baseline: 1.5630x; 1.1071x over previous
#include <cuda_runtime.h>
#include <cuda_fp16.h>
#include <cstdint>

// Problem constants (fixed by setup_inputs)
#define B_   8
#define QL   1024
#define SL   2048
#define DM   1024
#define H_   16
#define DH   64
#define QT   128          // q rows per CTA
#define STT  128          // s cols per chunk (K1)
#define NCH  (SL/STT)     // 16

#define KS_S 68           // K tile stride (floats): banks 4g+lt distinct for B-frags
#define PSH  136          // K1 e-staging stride in HALVES (word stride 68 -> banks 4g+lt)

// K1 smem bytes: Ks 3*128*68*4 + PsH 128*136*2 + mask 2048*4 + Rs 512*4
#define K1_SM_K    0
#define K1_SM_PS   (3*STT*KS_S*4)
#define K1_SM_M    (K1_SM_PS + QT*PSH*2)
#define K1_SM_RS   (K1_SM_M + SL*4)
#define K1_SMEM    (K1_SM_RS + 512*4)

// K2 config
#define KC   64           // k-chunk (s dimension)
#define NKC  (SL/KC)      // 32
#define AS_H 72           // e tile stride in halves (word stride 36 -> banks 4g+lt)
#define VS_S 68           // V f32 staging stride
#define VT_H 72           // V^T fp16 stride in halves
#define K2_SM_A    0
#define K2_SM_VT0  (2*QT*AS_H*2)                 // Vtmp f32 dbuf
#define K2_SM_VT   (K2_SM_VT0 + 2*KC*VS_S*4)     // Vt fp16
#define K2_SM_IV   (K2_SM_VT + KC*VT_H*2)
#define K2_SMEM    (K2_SM_IV + 512)

// scratch: per-(b,h,q) 1/rowsum, and fp16 e matrix
__device__ float  InvG[(size_t)B_ * H_ * QL];
__device__ __half EG[(size_t)B_ * H_ * QL * SL];   // 512 MB

__device__ __forceinline__ uint32_t tf32b(float x) {
    uint32_t u;
    asm("cvt.rna.tf32.f32 %0, %1;" : "=r"(u) : "f"(x));
    return u;
}

__device__ __forceinline__ void mma8(float d[4], const uint32_t a[4], const uint32_t b[2]) {
    asm("mma.sync.aligned.m16n8k8.row.col.f32.tf32.tf32.f32 "
        "{%0,%1,%2,%3},{%4,%5,%6,%7},{%8,%9},{%0,%1,%2,%3};\n"
        : "+f"(d[0]), "+f"(d[1]), "+f"(d[2]), "+f"(d[3])
        : "r"(a[0]), "r"(a[1]), "r"(a[2]), "r"(a[3]), "r"(b[0]), "r"(b[1]));
}

__device__ __forceinline__ void mma16(float d[4], const uint32_t a[4],
                                      uint32_t b0, uint32_t b1) {
    asm("mma.sync.aligned.m16n8k16.row.col.f32.f16.f16.f32 "
        "{%0,%1,%2,%3},{%4,%5,%6,%7},{%8,%9},{%0,%1,%2,%3};\n"
        : "+f"(d[0]), "+f"(d[1]), "+f"(d[2]), "+f"(d[3])
        : "r"(a[0]), "r"(a[1]), "r"(a[2]), "r"(a[3]), "r"(b0), "r"(b1));
}

__device__ __forceinline__ void cp_async16(uint32_t smem_addr, const void* gptr) {
    asm volatile("cp.async.cg.shared.global [%0], [%1], 16;\n"
                 :: "r"(smem_addr), "l"(gptr));
}
__device__ __forceinline__ void cp_commit() {
    asm volatile("cp.async.commit_group;\n");
}
__device__ __forceinline__ void cp_wait1() {
    asm volatile("cp.async.wait_group 1;\n");
}
__device__ __forceinline__ void cp_wait2() {
    asm volatile("cp.async.wait_group 2;\n");
}

// ===================== K1: single QK pass -> e=exp(z)*mask (fp16) + inv =====================
// 512 threads, warp grid 4(q) x 4(s). Q-frags in registers. e staged through smem,
// written to EG as full 256B rows (full lines, full sectors).
extern "C" __global__ void __launch_bounds__(512, 1)
mha_qk_kernel(const float* __restrict__ Qg, const float* __restrict__ Kg,
              const int* __restrict__ Mg) {
    extern __shared__ char smem[];
    float*  Ks  = (float*)(smem + K1_SM_K);
    __half* PsH = (__half*)(smem + K1_SM_PS);
    float*  Ms  = (float*)(smem + K1_SM_M);
    float*  Rs  = (float*)(smem + K1_SM_RS);

    const int tid = threadIdx.x;
    const int lane = tid & 31, wid = tid >> 5;
    const int g = lane >> 2, lt = lane & 3;
    const int wm = wid >> 2, wn = wid & 3;
    const int b = blockIdx.z, h = blockIdx.y, q0 = blockIdx.x * QT;

    const float* gkb = Kg + ((size_t)b * SL) * DM + h * DH;
    __half* geb = EG + ((size_t)((b * H_ + h) * QL + q0)) * SL;   // row stride SL
    const uint32_t ks_base = (uint32_t)__cvta_generic_to_shared(Ks);

    for (int j = tid; j < SL; j += 512) Ms[j] = (float)Mg[b * SL + j];

    // Q fragments -> registers (scale 1/8, tf32 RNA); rows wm*32 .. wm*32+31
    uint32_t qfr[2][8][4];
    {
        const float* gq = Qg + ((size_t)(b * QL + q0)) * DM + h * DH;
        #pragma unroll
        for (int mi = 0; mi < 2; mi++) {
            int r = wm * 32 + mi * 16 + g;
            #pragma unroll
            for (int kk = 0; kk < 8; kk++) {
                qfr[mi][kk][0] = tf32b(__ldg(gq + (size_t)r * DM + kk * 8 + lt) * 0.125f);
                qfr[mi][kk][1] = tf32b(__ldg(gq + (size_t)(r + 8) * DM + kk * 8 + lt) * 0.125f);
                qfr[mi][kk][2] = tf32b(__ldg(gq + (size_t)r * DM + kk * 8 + lt + 4) * 0.125f);
                qfr[mi][kk][3] = tf32b(__ldg(gq + (size_t)(r + 8) * DM + kk * 8 + lt + 4) * 0.125f);
            }
        }
    }

    // K staging coords: 512 threads x 4 float4 = 128 rows x 64 cols
    int srow[4], scol[4];
    #pragma unroll
    for (int j = 0; j < 4; j++) {
        int idx = tid + j * 512;
        srow[j] = idx >> 4;
        scol[j] = (idx & 15) << 2;
    }
    auto stage = [&](int sc, int bi) {
        const float* gk = gkb + (size_t)sc * STT * DM;
        const uint32_t kd = ks_base + (uint32_t)(bi * STT * KS_S) * 4;
        #pragma unroll
        for (int j = 0; j < 4; j++)
            cp_async16(kd + (uint32_t)(srow[j] * KS_S + scol[j]) * 4,
                       gk + (size_t)srow[j] * DM + scol[j]);
        cp_commit();
    };

    float rs_acc[2][2] = {{0.f, 0.f}, {0.f, 0.f}};
    stage(0, 0);
    stage(1, 1);

    for (int sc = 0; sc < NCH; sc++) {
        if (sc + 2 < NCH) stage(sc + 2, (sc + 2) % 3);
        else cp_commit();
        cp_wait2();
        __syncthreads();                       // (A) K chunk visible; prev PsH reads done
        const float* Kc = Ks + (sc % 3) * STT * KS_S;

        float acc[2][4][4];
        #pragma unroll
        for (int mi = 0; mi < 2; mi++)
            #pragma unroll
            for (int ni = 0; ni < 4; ni++)
                #pragma unroll
                for (int j = 0; j < 4; j++) acc[mi][ni][j] = 0.f;

        #pragma unroll
        for (int kk = 0; kk < 8; kk++) {
            #pragma unroll
            for (int ni = 0; ni < 4; ni++) {
                int c = wn * 32 + ni * 8 + g;
                uint32_t bfr[2];
                bfr[0] = tf32b(Kc[c * KS_S + kk * 8 + lt]);
                bfr[1] = tf32b(Kc[c * KS_S + kk * 8 + lt + 4]);
                mma8(acc[0][ni], qfr[0][kk], bfr);
                mma8(acc[1][ni], qfr[1][kk], bfr);
            }
        }

        // epilogue: e = exp(z)*mask -> PsH (fp16); rowsum from ROUNDED values
        const int s0 = sc * STT;
        #pragma unroll
        for (int mi = 0; mi < 2; mi++)
            #pragma unroll
            for (int half = 0; half < 2; half++) {
                int r = wm * 32 + mi * 16 + g + half * 8;
                float rloc = 0.f;
                #pragma unroll
                for (int ni = 0; ni < 4; ni++) {
                    int cc = wn * 32 + ni * 8 + 2 * lt;
                    float ex = __expf(acc[mi][ni][half * 2 + 0]) * Ms[s0 + cc];
                    float ey = __expf(acc[mi][ni][half * 2 + 1]) * Ms[s0 + cc + 1];
                    __half2 hv = __floats2half2_rn(ex, ey);
                    float2 fr = __half22float2(hv);
                    rloc += fr.x + fr.y;
                    *(__half2*)(PsH + r * PSH + cc) = hv;   // conflict-free STS.32
                }
                rs_acc[mi][half] += rloc;
            }
        __syncthreads();                       // (B) PsH complete

        // coalesced fp16 store: full 256B rows -> EG (full lines, full sectors)
        #pragma unroll
        for (int j = 0; j < 4; j++) {
            int idx = tid + j * 512;           // 128 rows x 16 x16B units
            int r = idx >> 4, u = idx & 15;
            uint4 v = *(const uint4*)((const char*)PsH + r * (PSH * 2) + u * 16);
            __stcs((uint4*)(geb + (size_t)r * SL + s0 + u * 8), v);
        }
        // no end sync needed: sync (A) of the next iteration orders PsH reuse
    }

    // reduce rowsums: over lt within quad, then over wn via smem
    #pragma unroll
    for (int mi = 0; mi < 2; mi++)
        #pragma unroll
        for (int half = 0; half < 2; half++) {
            float v = rs_acc[mi][half];
            v += __shfl_xor_sync(0xffffffffu, v, 1);
            v += __shfl_xor_sync(0xffffffffu, v, 2);
            if (lt == 0) {
                int r = wm * 32 + mi * 16 + g + half * 8;
                Rs[wn * 128 + r] = v;
            }
        }
    __syncthreads();
    if (tid < QT) {
        float s = Rs[tid] + Rs[128 + tid] + Rs[256 + tid] + Rs[384 + tid];
        InvG[((size_t)(b * H_ + h)) * QL + q0 + tid] = 1.0f / (s + 1e-13f);
    }
}

// ===================== K2: attn = e*inv (f32) + O = (e @ V) * inv, fp16 mma =====================
extern "C" __global__ void __launch_bounds__(256, 2)
mha_pv_kernel(const float* __restrict__ Vg, float* __restrict__ Ag,
              float* __restrict__ Og) {
    extern __shared__ char smem[];
    __half* As   = (__half*)(smem + K2_SM_A);     // 2 x 128 x AS_H halves (e)
    float*  Vtmp = (float*)(smem + K2_SM_VT0);    // 2 x 64 x VS_S f32
    __half* Vt   = (__half*)(smem + K2_SM_VT);    // 64 x VT_H halves (V^T fp16)
    float*  Iv   = (float*)(smem + K2_SM_IV);     // 128 inv values

    const int tid = threadIdx.x;
    const int lane = tid & 31, wid = tid >> 5;
    const int g = lane >> 2, lt = lane & 3;
    const int wm = wid >> 1, wn = wid & 1;   // 4(q) x 2(dv), warp tile 32x32
    const int b = blockIdx.z, h = blockIdx.y, q0 = blockIdx.x * QT;

    const uint32_t as_base = (uint32_t)__cvta_generic_to_shared(As);
    const uint32_t vs_base = (uint32_t)__cvta_generic_to_shared(Vtmp);

    if (tid < QT) Iv[tid] = InvG[((size_t)(b * H_ + h)) * QL + q0 + tid];

    // A staging: 128 rows x 64 halves (128B/row) -> 1024 x 16B ops
    int ar[4], ac[4];
    #pragma unroll
    for (int j = 0; j < 4; j++) {
        int idx = tid + j * 256;
        ar[j] = idx >> 3;
        ac[j] = (idx & 7) * 8;     // half units
    }
    // V staging: 64 rows x 64 floats
    int vr[4], vc[4];
    #pragma unroll
    for (int j = 0; j < 4; j++) {
        int idx = tid + j * 256;
        vr[j] = idx >> 4;
        vc[j] = (idx & 15) << 2;
    }

    const __half* geb = EG + ((size_t)((b * H_ + h) * QL + q0)) * SL;  // row stride SL
    float* gab = Ag + ((size_t)((b * QL + q0) * H_ + h)) * SL;         // row stride H_*SL
    const float* gvb = Vg + ((size_t)b * SL) * DM + h * DH;

    auto stage = [&](int kc, int bi) {
        const int s0 = kc * KC;
        const uint32_t ad = as_base + (uint32_t)(bi * QT * AS_H) * 2;
        #pragma unroll
        for (int j = 0; j < 4; j++)
            cp_async16(ad + (uint32_t)(ar[j] * AS_H + ac[j]) * 2,
                       geb + (size_t)ar[j] * SL + s0 + ac[j]);
        const uint32_t vd = vs_base + (uint32_t)(bi * KC * VS_S) * 4;
        #pragma unroll
        for (int j = 0; j < 4; j++)
            cp_async16(vd + (uint32_t)(vr[j] * VS_S + vc[j]) * 4,
                       gvb + (size_t)(kc * KC + vr[j]) * DM + vc[j]);
        cp_commit();
    };

    float oacc[2][4][4];
    #pragma unroll
    for (int mi = 0; mi < 2; mi++)
        #pragma unroll
        for (int ni = 0; ni < 4; ni++)
            #pragma unroll
            for (int j = 0; j < 4; j++) oacc[mi][ni][j] = 0.f;

    stage(0, 0);

    for (int kc = 0; kc < NKC; kc++) {
        if (kc + 1 < NKC) stage(kc + 1, (kc + 1) & 1);
        else cp_commit();
        cp_wait1();
        __syncthreads();

        const __half* Ac = As + (kc & 1) * QT * AS_H;
        const float*  Vsrc = Vtmp + (kc & 1) * KC * VS_S;

        // transpose+convert V chunk: Vtmp[k][c] f32 -> Vt[c][k] fp16 (conflict-free both sides)
        {
            int c = g + 8 * wid;                 // wid < 8 -> c < 64
            #pragma unroll
            for (int j = 0; j < 8; j++) {
                int k0 = lt + 4 * j;             // half2 index, k = 2k0, 2k0+1
                float x = Vsrc[(2 * k0) * VS_S + c];
                float y = Vsrc[(2 * k0 + 1) * VS_S + c];
                *(__half2*)(Vt + c * VT_H + 2 * k0) = __floats2half2_rn(x, y);
            }
        }
        __syncthreads();

        // PV mma: m16n8k16 fp16, zero conversions
        #pragma unroll
        for (int kk = 0; kk < 4; kk++) {
            uint32_t a[2][4];
            #pragma unroll
            for (int mi = 0; mi < 2; mi++) {
                int r = wm * 32 + mi * 16 + g;
                const __half* ap = Ac + r * AS_H + kk * 16 + 2 * lt;
                a[mi][0] = *(const uint32_t*)(ap);
                a[mi][1] = *(const uint32_t*)(ap + 8 * AS_H);
                a[mi][2] = *(const uint32_t*)(ap + 8);
                a[mi][3] = *(const uint32_t*)(ap + 8 * AS_H + 8);
            }
            #pragma unroll
            for (int ni = 0; ni < 4; ni++) {
                int c = wn * 32 + ni * 8 + g;
                const __half* bp = Vt + c * VT_H + kk * 16 + 2 * lt;
                uint32_t b0 = *(const uint32_t*)(bp);
                uint32_t b1 = *(const uint32_t*)(bp + 8);
                mma16(oacc[0][ni], a[0], b0, b1);
                mma16(oacc[1][ni], a[1], b0, b1);
            }
        }

        // normalized attention write: attn = float(e_fp16) * inv[row], f32, coalesced
        const int s0 = kc * KC;
        #pragma unroll
        for (int j = 0; j < 8; j++) {
            int idx = tid + j * 256;            // 128 rows x 16 float4
            int r = idx >> 4, c4 = (idx & 15) << 2;
            __half2 ha = *(const __half2*)(Ac + r * AS_H + c4);
            __half2 hb = *(const __half2*)(Ac + r * AS_H + c4 + 2);
            float2 fa = __half22float2(ha), fb = __half22float2(hb);
            float iv = Iv[r];
            float4 v = make_float4(fa.x * iv, fa.y * iv, fb.x * iv, fb.y * iv);
            __stwt((float4*)(gab + (size_t)r * (H_ * SL) + s0 + c4), v);
        }
        __syncthreads();   // buffers (As/Vtmp/Vt) free before restage
    }

    // ---- write O tile, scaled by inv per row ----
    #pragma unroll
    for (int mi = 0; mi < 2; mi++) {
        int r = wm * 32 + mi * 16 + g;
        float iv0 = Iv[r], iv1 = Iv[r + 8];
        float* go = Og + ((size_t)(b * QL + q0 + r)) * DM + h * DH + wn * 32;
        #pragma unroll
        for (int ni = 0; ni < 4; ni++) {
            int c = ni * 8 + 2 * lt;
            float2 v0; v0.x = oacc[mi][ni][0] * iv0; v0.y = oacc[mi][ni][1] * iv0;
            float2 v1; v1.x = oacc[mi][ni][2] * iv1; v1.y = oacc[mi][ni][3] * iv1;
            __stcs((float2*)(go + c), v0);
            __stcs((float2*)(go + (size_t)8 * DM + c), v1);
        }
    }
}

extern "C" void kernel_launch(void* const* d_in, const int* in_sizes, int n_in,
                              void* d_out, int out_size) {
    const float* Qg = (const float*)d_in[0];
    const float* Kg = (const float*)d_in[1];
    const float* Vg = (const float*)d_in[2];
    const int*   Mg = (const int*)d_in[3];

    float* Og = (float*)d_out;
    float* Ag = Og + (size_t)B_ * QL * DM;   // attention region of d_out

    cudaFuncSetAttribute(mha_qk_kernel,
                         cudaFuncAttributeMaxDynamicSharedMemorySize, K1_SMEM);
    cudaFuncSetAttribute(mha_pv_kernel,
                         cudaFuncAttributeMaxDynamicSharedMemorySize, K2_SMEM);

    dim3 grid(QL / QT, H_, B_);
    mha_qk_kernel<<<grid, 512, K1_SMEM>>>(Qg, Kg, Mg);
    mha_pv_kernel<<<grid, 256, K2_SMEM>>>(Vg, Ag, Og);
}

// round 16
// speedup vs baseline: 1.6998x; 1.0875x over previous
#include <cuda_runtime.h>
#include <cuda_fp16.h>
#include <cstdint>

// Problem constants (fixed by setup_inputs)
#define B_   8
#define QL   1024
#define SL   2048
#define DM   1024
#define H_   16
#define DH   64
#define QT   128          // q rows per CTA

// ---- K1 config: 256 threads, occ 2, STT=64 ----
#define STT  64           // s cols per chunk (K1)
#define NCH  (SL/STT)     // 32
#define KS_S 68           // K tile stride (floats): banks 4g+lt distinct for B-frags
#define PSH2 72           // K1 e-staging stride in HALVES (word stride 36 -> banks 4g+lt)

// K1 smem bytes: Ks 3*64*68*4 + PsH 128*72*2 + mask 2048*4 + Rs 256*4
#define K1_SM_K    0
#define K1_SM_PS   (3*STT*KS_S*4)
#define K1_SM_M    (K1_SM_PS + QT*PSH2*2)
#define K1_SM_RS   (K1_SM_M + SL*4)
#define K1_SMEM    (K1_SM_RS + 256*4)          // ~80 KB -> 2 CTAs/SM

// ---- K2 config (unchanged from R12) ----
#define KC   64           // k-chunk (s dimension)
#define NKC  (SL/KC)      // 32
#define AS_H 72           // e tile stride in halves (word stride 36 -> banks 4g+lt)
#define VS_S 68           // V f32 staging stride
#define VT_H 72           // V^T fp16 stride in halves
#define K2_SM_A    0
#define K2_SM_VT0  (2*QT*AS_H*2)                 // Vtmp f32 dbuf
#define K2_SM_VT   (K2_SM_VT0 + 2*KC*VS_S*4)     // Vt fp16
#define K2_SM_IV   (K2_SM_VT + KC*VT_H*2)
#define K2_SMEM    (K2_SM_IV + 512)

// scratch: per-(b,h,q) 1/rowsum, and fp16 e matrix
__device__ float  InvG[(size_t)B_ * H_ * QL];
__device__ __half EG[(size_t)B_ * H_ * QL * SL];   // 512 MB

__device__ __forceinline__ uint32_t tf32b(float x) {
    uint32_t u;
    asm("cvt.rna.tf32.f32 %0, %1;" : "=r"(u) : "f"(x));
    return u;
}

__device__ __forceinline__ void mma8(float d[4], const uint32_t a[4], const uint32_t b[2]) {
    asm("mma.sync.aligned.m16n8k8.row.col.f32.tf32.tf32.f32 "
        "{%0,%1,%2,%3},{%4,%5,%6,%7},{%8,%9},{%0,%1,%2,%3};\n"
        : "+f"(d[0]), "+f"(d[1]), "+f"(d[2]), "+f"(d[3])
        : "r"(a[0]), "r"(a[1]), "r"(a[2]), "r"(a[3]), "r"(b[0]), "r"(b[1]));
}

__device__ __forceinline__ void mma16(float d[4], const uint32_t a[4],
                                      uint32_t b0, uint32_t b1) {
    asm("mma.sync.aligned.m16n8k16.row.col.f32.f16.f16.f32 "
        "{%0,%1,%2,%3},{%4,%5,%6,%7},{%8,%9},{%0,%1,%2,%3};\n"
        : "+f"(d[0]), "+f"(d[1]), "+f"(d[2]), "+f"(d[3])
        : "r"(a[0]), "r"(a[1]), "r"(a[2]), "r"(a[3]), "r"(b0), "r"(b1));
}

__device__ __forceinline__ void cp_async16(uint32_t smem_addr, const void* gptr) {
    asm volatile("cp.async.cg.shared.global [%0], [%1], 16;\n"
                 :: "r"(smem_addr), "l"(gptr));
}
__device__ __forceinline__ void cp_commit() {
    asm volatile("cp.async.commit_group;\n");
}
__device__ __forceinline__ void cp_wait1() {
    asm volatile("cp.async.wait_group 1;\n");
}
__device__ __forceinline__ void cp_wait2() {
    asm volatile("cp.async.wait_group 2;\n");
}

// ===================== K1: single QK pass -> e=exp(z)*mask (fp16) + inv =====================
// 256 threads, occ 2, warp grid 4(q) x 2(s), warp tile 32x32, STT=64 chunks.
// Q-frags in registers; K triple-buffered via cp.async; e staged through smem and
// written to EG as full 128B rows. Two CTAs/SM interleave to fill dependency stalls.
extern "C" __global__ void __launch_bounds__(256, 2)
mha_qk_kernel(const float* __restrict__ Qg, const float* __restrict__ Kg,
              const int* __restrict__ Mg) {
    extern __shared__ char smem[];
    float*  Ks  = (float*)(smem + K1_SM_K);
    __half* PsH = (__half*)(smem + K1_SM_PS);
    float*  Ms  = (float*)(smem + K1_SM_M);
    float*  Rs  = (float*)(smem + K1_SM_RS);

    const int tid = threadIdx.x;
    const int lane = tid & 31, wid = tid >> 5;
    const int g = lane >> 2, lt = lane & 3;
    const int wm = wid >> 1, wn = wid & 1;
    const int b = blockIdx.z, h = blockIdx.y, q0 = blockIdx.x * QT;

    const float* gkb = Kg + ((size_t)b * SL) * DM + h * DH;
    __half* geb = EG + ((size_t)((b * H_ + h) * QL + q0)) * SL;   // row stride SL
    const uint32_t ks_base = (uint32_t)__cvta_generic_to_shared(Ks);

    for (int j = tid; j < SL; j += 256) Ms[j] = (float)Mg[b * SL + j];

    // Q fragments -> registers (scale 1/8, tf32 RNA); rows wm*32 .. wm*32+31
    uint32_t qfr[2][8][4];
    {
        const float* gq = Qg + ((size_t)(b * QL + q0)) * DM + h * DH;
        #pragma unroll
        for (int mi = 0; mi < 2; mi++) {
            int r = wm * 32 + mi * 16 + g;
            #pragma unroll
            for (int kk = 0; kk < 8; kk++) {
                qfr[mi][kk][0] = tf32b(__ldg(gq + (size_t)r * DM + kk * 8 + lt) * 0.125f);
                qfr[mi][kk][1] = tf32b(__ldg(gq + (size_t)(r + 8) * DM + kk * 8 + lt) * 0.125f);
                qfr[mi][kk][2] = tf32b(__ldg(gq + (size_t)r * DM + kk * 8 + lt + 4) * 0.125f);
                qfr[mi][kk][3] = tf32b(__ldg(gq + (size_t)(r + 8) * DM + kk * 8 + lt + 4) * 0.125f);
            }
        }
    }

    // K staging coords: 256 threads x 4 float4 = 64 rows x 64 cols
    int srow[4], scol[4];
    #pragma unroll
    for (int j = 0; j < 4; j++) {
        int idx = tid + j * 256;
        srow[j] = idx >> 4;
        scol[j] = (idx & 15) << 2;
    }
    auto stage = [&](int sc, int bi) {
        const float* gk = gkb + (size_t)sc * STT * DM;
        const uint32_t kd = ks_base + (uint32_t)(bi * STT * KS_S) * 4;
        #pragma unroll
        for (int j = 0; j < 4; j++)
            cp_async16(kd + (uint32_t)(srow[j] * KS_S + scol[j]) * 4,
                       gk + (size_t)srow[j] * DM + scol[j]);
        cp_commit();
    };

    float rs_acc[2][2] = {{0.f, 0.f}, {0.f, 0.f}};
    stage(0, 0);
    stage(1, 1);

    for (int sc = 0; sc < NCH; sc++) {
        if (sc + 2 < NCH) stage(sc + 2, (sc + 2) % 3);
        else cp_commit();
        cp_wait2();
        __syncthreads();                       // (A) K chunk visible; prev PsH reads done
        const float* Kc = Ks + (sc % 3) * STT * KS_S;

        float acc[2][4][4];
        #pragma unroll
        for (int mi = 0; mi < 2; mi++)
            #pragma unroll
            for (int ni = 0; ni < 4; ni++)
                #pragma unroll
                for (int j = 0; j < 4; j++) acc[mi][ni][j] = 0.f;

        #pragma unroll
        for (int kk = 0; kk < 8; kk++) {
            #pragma unroll
            for (int ni = 0; ni < 4; ni++) {
                int c = wn * 32 + ni * 8 + g;
                uint32_t bfr[2];
                bfr[0] = tf32b(Kc[c * KS_S + kk * 8 + lt]);
                bfr[1] = tf32b(Kc[c * KS_S + kk * 8 + lt + 4]);
                mma8(acc[0][ni], qfr[0][kk], bfr);
                mma8(acc[1][ni], qfr[1][kk], bfr);
            }
        }

        // epilogue: e = exp(z)*mask -> PsH (fp16); rowsum from ROUNDED values
        const int s0 = sc * STT;
        #pragma unroll
        for (int mi = 0; mi < 2; mi++)
            #pragma unroll
            for (int half = 0; half < 2; half++) {
                int r = wm * 32 + mi * 16 + g + half * 8;
                float rloc = 0.f;
                #pragma unroll
                for (int ni = 0; ni < 4; ni++) {
                    int cc = wn * 32 + ni * 8 + 2 * lt;
                    float ex = __expf(acc[mi][ni][half * 2 + 0]) * Ms[s0 + cc];
                    float ey = __expf(acc[mi][ni][half * 2 + 1]) * Ms[s0 + cc + 1];
                    __half2 hv = __floats2half2_rn(ex, ey);
                    float2 fr = __half22float2(hv);
                    rloc += fr.x + fr.y;
                    *(__half2*)(PsH + r * PSH2 + cc) = hv;   // conflict-free STS.32
                }
                rs_acc[mi][half] += rloc;
            }
        __syncthreads();                       // (B) PsH complete

        // coalesced fp16 store: full 128B rows -> EG (full lines, full sectors)
        #pragma unroll
        for (int j = 0; j < 4; j++) {
            int idx = tid + j * 256;           // 128 rows x 8 x16B units
            int r = idx >> 3, u = idx & 7;
            uint4 v = *(const uint4*)((const char*)PsH + r * (PSH2 * 2) + u * 16);
            __stcs((uint4*)(geb + (size_t)r * SL + s0 + u * 8), v);
        }
        // no end sync: sync (A) of next iter orders PsH reuse
    }

    // reduce rowsums: over lt within quad, then over wn via smem
    #pragma unroll
    for (int mi = 0; mi < 2; mi++)
        #pragma unroll
        for (int half = 0; half < 2; half++) {
            float v = rs_acc[mi][half];
            v += __shfl_xor_sync(0xffffffffu, v, 1);
            v += __shfl_xor_sync(0xffffffffu, v, 2);
            if (lt == 0) {
                int r = wm * 32 + mi * 16 + g + half * 8;
                Rs[wn * 128 + r] = v;
            }
        }
    __syncthreads();
    if (tid < QT) {
        float s = Rs[tid] + Rs[128 + tid];
        InvG[((size_t)(b * H_ + h)) * QL + q0 + tid] = 1.0f / (s + 1e-13f);
    }
}

// ===================== K2: attn = e*inv (f32) + O = (e @ V) * inv, fp16 mma =====================
extern "C" __global__ void __launch_bounds__(256, 2)
mha_pv_kernel(const float* __restrict__ Vg, float* __restrict__ Ag,
              float* __restrict__ Og) {
    extern __shared__ char smem[];
    __half* As   = (__half*)(smem + K2_SM_A);     // 2 x 128 x AS_H halves (e)
    float*  Vtmp = (float*)(smem + K2_SM_VT0);    // 2 x 64 x VS_S f32
    __half* Vt   = (__half*)(smem + K2_SM_VT);    // 64 x VT_H halves (V^T fp16)
    float*  Iv   = (float*)(smem + K2_SM_IV);     // 128 inv values

    const int tid = threadIdx.x;
    const int lane = tid & 31, wid = tid >> 5;
    const int g = lane >> 2, lt = lane & 3;
    const int wm = wid >> 1, wn = wid & 1;   // 4(q) x 2(dv), warp tile 32x32
    const int b = blockIdx.z, h = blockIdx.y, q0 = blockIdx.x * QT;

    const uint32_t as_base = (uint32_t)__cvta_generic_to_shared(As);
    const uint32_t vs_base = (uint32_t)__cvta_generic_to_shared(Vtmp);

    if (tid < QT) Iv[tid] = InvG[((size_t)(b * H_ + h)) * QL + q0 + tid];

    // A staging: 128 rows x 64 halves (128B/row) -> 1024 x 16B ops
    int ar[4], ac[4];
    #pragma unroll
    for (int j = 0; j < 4; j++) {
        int idx = tid + j * 256;
        ar[j] = idx >> 3;
        ac[j] = (idx & 7) * 8;     // half units
    }
    // V staging: 64 rows x 64 floats
    int vr[4], vc[4];
    #pragma unroll
    for (int j = 0; j < 4; j++) {
        int idx = tid + j * 256;
        vr[j] = idx >> 4;
        vc[j] = (idx & 15) << 2;
    }

    const __half* geb = EG + ((size_t)((b * H_ + h) * QL + q0)) * SL;  // row stride SL
    float* gab = Ag + ((size_t)((b * QL + q0) * H_ + h)) * SL;         // row stride H_*SL
    const float* gvb = Vg + ((size_t)b * SL) * DM + h * DH;

    auto stage = [&](int kc, int bi) {
        const int s0 = kc * KC;
        const uint32_t ad = as_base + (uint32_t)(bi * QT * AS_H) * 2;
        #pragma unroll
        for (int j = 0; j < 4; j++)
            cp_async16(ad + (uint32_t)(ar[j] * AS_H + ac[j]) * 2,
                       geb + (size_t)ar[j] * SL + s0 + ac[j]);
        const uint32_t vd = vs_base + (uint32_t)(bi * KC * VS_S) * 4;
        #pragma unroll
        for (int j = 0; j < 4; j++)
            cp_async16(vd + (uint32_t)(vr[j] * VS_S + vc[j]) * 4,
                       gvb + (size_t)(kc * KC + vr[j]) * DM + vc[j]);
        cp_commit();
    };

    float oacc[2][4][4];
    #pragma unroll
    for (int mi = 0; mi < 2; mi++)
        #pragma unroll
        for (int ni = 0; ni < 4; ni++)
            #pragma unroll
            for (int j = 0; j < 4; j++) oacc[mi][ni][j] = 0.f;

    stage(0, 0);

    for (int kc = 0; kc < NKC; kc++) {
        if (kc + 1 < NKC) stage(kc + 1, (kc + 1) & 1);
        else cp_commit();
        cp_wait1();
        __syncthreads();

        const __half* Ac = As + (kc & 1) * QT * AS_H;
        const float*  Vsrc = Vtmp + (kc & 1) * KC * VS_S;

        // transpose+convert V chunk: Vtmp[k][c] f32 -> Vt[c][k] fp16
        {
            int c = g + 8 * wid;                 // wid < 8 -> c < 64
            #pragma unroll
            for (int j = 0; j < 8; j++) {
                int k0 = lt + 4 * j;             // half2 index, k = 2k0, 2k0+1
                float x = Vsrc[(2 * k0) * VS_S + c];
                float y = Vsrc[(2 * k0 + 1) * VS_S + c];
                *(__half2*)(Vt + c * VT_H + 2 * k0) = __floats2half2_rn(x, y);
            }
        }
        __syncthreads();

        // PV mma: m16n8k16 fp16, zero conversions
        #pragma unroll
        for (int kk = 0; kk < 4; kk++) {
            uint32_t a[2][4];
            #pragma unroll
            for (int mi = 0; mi < 2; mi++) {
                int r = wm * 32 + mi * 16 + g;
                const __half* ap = Ac + r * AS_H + kk * 16 + 2 * lt;
                a[mi][0] = *(const uint32_t*)(ap);
                a[mi][1] = *(const uint32_t*)(ap + 8 * AS_H);
                a[mi][2] = *(const uint32_t*)(ap + 8);
                a[mi][3] = *(const uint32_t*)(ap + 8 * AS_H + 8);
            }
            #pragma unroll
            for (int ni = 0; ni < 4; ni++) {
                int c = wn * 32 + ni * 8 + g;
                const __half* bp = Vt + c * VT_H + kk * 16 + 2 * lt;
                uint32_t b0 = *(const uint32_t*)(bp);
                uint32_t b1 = *(const uint32_t*)(bp + 8);
                mma16(oacc[0][ni], a[0], b0, b1);
                mma16(oacc[1][ni], a[1], b0, b1);
            }
        }

        // normalized attention write: attn = float(e_fp16) * inv[row], f32, coalesced
        const int s0 = kc * KC;
        #pragma unroll
        for (int j = 0; j < 8; j++) {
            int idx = tid + j * 256;            // 128 rows x 16 float4
            int r = idx >> 4, c4 = (idx & 15) << 2;
            __half2 ha = *(const __half2*)(Ac + r * AS_H + c4);
            __half2 hb = *(const __half2*)(Ac + r * AS_H + c4 + 2);
            float2 fa = __half22float2(ha), fb = __half22float2(hb);
            float iv = Iv[r];
            float4 v = make_float4(fa.x * iv, fa.y * iv, fb.x * iv, fb.y * iv);
            __stwt((float4*)(gab + (size_t)r * (H_ * SL) + s0 + c4), v);
        }
        __syncthreads();   // buffers (As/Vtmp/Vt) free before restage
    }

    // ---- write O tile, scaled by inv per row ----
    #pragma unroll
    for (int mi = 0; mi < 2; mi++) {
        int r = wm * 32 + mi * 16 + g;
        float iv0 = Iv[r], iv1 = Iv[r + 8];
        float* go = Og + ((size_t)(b * QL + q0 + r)) * DM + h * DH + wn * 32;
        #pragma unroll
        for (int ni = 0; ni < 4; ni++) {
            int c = ni * 8 + 2 * lt;
            float2 v0; v0.x = oacc[mi][ni][0] * iv0; v0.y = oacc[mi][ni][1] * iv0;
            float2 v1; v1.x = oacc[mi][ni][2] * iv1; v1.y = oacc[mi][ni][3] * iv1;
            __stcs((float2*)(go + c), v0);
            __stcs((float2*)(go + (size_t)8 * DM + c), v1);
        }
    }
}

extern "C" void kernel_launch(void* const* d_in, const int* in_sizes, int n_in,
                              void* d_out, int out_size) {
    const float* Qg = (const float*)d_in[0];
    const float* Kg = (const float*)d_in[1];
    const float* Vg = (const float*)d_in[2];
    const int*   Mg = (const int*)d_in[3];

    float* Og = (float*)d_out;
    float* Ag = Og + (size_t)B_ * QL * DM;   // attention region of d_out

    cudaFuncSetAttribute(mha_qk_kernel,
                         cudaFuncAttributeMaxDynamicSharedMemorySize, K1_SMEM);
    cudaFuncSetAttribute(mha_pv_kernel,
                         cudaFuncAttributeMaxDynamicSharedMemorySize, K2_SMEM);

    dim3 grid(QL / QT, H_, B_);
    mha_qk_kernel<<<grid, 256, K1_SMEM>>>(Qg, Kg, Mg);
    mha_pv_kernel<<<grid, 256, K2_SMEM>>>(Vg, Ag, Og);
}